// round 2
// baseline (speedup 1.0000x reference)
#include <cuda_runtime.h>

#define BSZ  512
#define TLEN 512
#define IDIM 128
#define HDIM 50
#define ODIM 10
#define GDIM 200              // 4*H
#define BT   (BSZ * TLEN)     // 262144 rows

// ---- scratch (device globals; no allocation allowed) ----
__device__ float g_xT[IDIM * BT];     // x transposed: [k][row], 134 MB
__device__ float g_Wt[IDIM * GDIM];   // W_ih transposed: [k][g]
__device__ float g_bias[GDIM];        // b_ih + b_hh
__device__ float g_xp[BT * GDIM];     // x_proj: [row][g], 210 MB

// ============================================================
// Kernel 0: transpose W_ih -> [k][g], and bias sum
// ============================================================
__global__ void prep_w(const float* __restrict__ W_ih,
                       const float* __restrict__ b_ih,
                       const float* __restrict__ b_hh) {
    int t = threadIdx.x;
    for (int idx = t; idx < IDIM * GDIM; idx += 256) {
        int g = idx / IDIM, k = idx % IDIM;
        g_Wt[k * GDIM + g] = W_ih[idx];
    }
    if (t < GDIM) g_bias[t] = b_ih[t] + b_hh[t];
}

// ============================================================
// Kernel 1: transpose x [BT][128] -> g_xT [128][BT]
// Standard 32x32 SMEM tile transpose, coalesced both sides.
// ============================================================
__global__ void transpose_x(const float* __restrict__ x) {
    __shared__ float tile[32][33];
    int r0 = blockIdx.x * 32;
    int k0 = blockIdx.y * 32;
    int tx = threadIdx.x, ty = threadIdx.y;   // (32, 8)
#pragma unroll
    for (int i = 0; i < 32; i += 8)
        tile[ty + i][tx] = x[(r0 + ty + i) * IDIM + k0 + tx];
    __syncthreads();
#pragma unroll
    for (int i = 0; i < 32; i += 8)
        g_xT[(k0 + ty + i) * BT + r0 + tx] = tile[tx][ty + i];
}

// ============================================================
// Kernel 2: GEMM  g_xp[row][g] = sum_k xT[k][row] * Wt[k][g] + bias[g]
// M = 262144, N = 200, K = 128.
// Block: 64 rows x 200 cols. 256 threads; (tm=tid&7, tn=tid>>3),
// tn<25 compute an 8x8 register tile; extra threads only help load.
// SMEM tiles are [k][...] so compute reads are float4, conflict-free.
// ============================================================
#define MT 64
#define KT 32

__global__ __launch_bounds__(256, 2) void gemm_xproj() {
    __shared__ float xs[KT][MT];      // 8 KB
    __shared__ float ws[KT][GDIM];    // 25.6 KB
    const int tid = threadIdx.x;
    const int gr0 = blockIdx.x * MT;
    const int tm = tid & 7;           // 0..7   -> rows tm*8 .. tm*8+7
    const int tn = tid >> 3;          // 0..31  -> cols tn*8 .. (active if <25)
    const bool active = (tn < 25);

    float acc[8][8];
#pragma unroll
    for (int i = 0; i < 8; i++)
#pragma unroll
        for (int j = 0; j < 8; j++) acc[i][j] = 0.f;

    for (int kb = 0; kb < IDIM; kb += KT) {
        __syncthreads();
        // load x tile: 32 k-rows x 64 rows = 512 float4, coalesced from g_xT
        {
            int idx = tid;
#pragma unroll
            for (int r = 0; r < 2; r++, idx += 256) {
                int k = idx >> 4, c = idx & 15;
                *(float4*)&xs[k][c * 4] =
                    *(const float4*)&g_xT[(kb + k) * BT + gr0 + c * 4];
            }
        }
        // load W tile: 32 k-rows x 200 g = 1600 float4
        for (int idx = tid; idx < KT * GDIM / 4; idx += 256) {
            int k = idx / 50, c = idx % 50;
            *(float4*)&ws[k][c * 4] =
                *(const float4*)&g_Wt[(kb + k) * GDIM + c * 4];
        }
        __syncthreads();

        if (active) {
#pragma unroll 8
            for (int k = 0; k < KT; k++) {
                float4 x0 = *(float4*)&xs[k][tm * 8];
                float4 x1 = *(float4*)&xs[k][tm * 8 + 4];
                float4 w0 = *(float4*)&ws[k][tn * 8];
                float4 w1 = *(float4*)&ws[k][tn * 8 + 4];
                float xv[8] = {x0.x, x0.y, x0.z, x0.w, x1.x, x1.y, x1.z, x1.w};
                float wv[8] = {w0.x, w0.y, w0.z, w0.w, w1.x, w1.y, w1.z, w1.w};
#pragma unroll
                for (int i = 0; i < 8; i++)
#pragma unroll
                    for (int j = 0; j < 8; j++)
                        acc[i][j] = fmaf(xv[i], wv[j], acc[i][j]);
            }
        }
    }

    if (active) {
        float bv[8];
#pragma unroll
        for (int j = 0; j < 8; j++) bv[j] = g_bias[tn * 8 + j];
#pragma unroll
        for (int i = 0; i < 8; i++) {
            int row = gr0 + tm * 8 + i;
            float4 o0 = make_float4(acc[i][0] + bv[0], acc[i][1] + bv[1],
                                    acc[i][2] + bv[2], acc[i][3] + bv[3]);
            float4 o1 = make_float4(acc[i][4] + bv[4], acc[i][5] + bv[5],
                                    acc[i][6] + bv[6], acc[i][7] + bv[7]);
            *(float4*)&g_xp[row * GDIM + tn * 8]     = o0;
            *(float4*)&g_xp[row * GDIM + tn * 8 + 4] = o1;
        }
    }
}

// ============================================================
// Kernel 3: sequential LSTM recurrence + FC head.
// One block per batch element. 224 threads (7 warps); threads 0..199
// each own one gate row of W_hh in registers. h, c-update gates in SMEM.
// Branch-free activations: tanh(x) = 2*sigmoid(2x) - 1.
// ============================================================
__device__ __forceinline__ float fast_sigmoid(float x) {
    return 1.f / (1.f + __expf(-x));
}

__global__ __launch_bounds__(224) void lstm_rec(
    const float* __restrict__ W_hh, const float* __restrict__ W_fc,
    const float* __restrict__ b_fc, float* __restrict__ out)
{
    __shared__ float h_sh[HDIM];
    __shared__ float gate_sh[GDIM];
    const int b = blockIdx.x;
    const int g = threadIdx.x;          // gate index, active if < 200

    float w[HDIM];
    if (g < GDIM) {
#pragma unroll
        for (int j = 0; j < HDIM; j++) w[j] = W_hh[g * HDIM + j];
    }
    if (g < HDIM) h_sh[g] = 0.f;
    float c = 0.f;

    const float* xp = g_xp + b * (TLEN * GDIM);
    float xnext = (g < GDIM) ? xp[g] : 0.f;
    const bool isg = (g >= 2 * HDIM && g < 3 * HDIM);   // the tanh gate
    __syncthreads();

    for (int t = 0; t < TLEN; t++) {
        if (g < GDIM) {
            float a0 = xnext, a1 = 0.f;
            if (t + 1 < TLEN) xnext = xp[(t + 1) * GDIM + g];  // prefetch
#pragma unroll
            for (int j = 0; j < HDIM; j += 2) {
                a0 = fmaf(h_sh[j],     w[j],     a0);
                a1 = fmaf(h_sh[j + 1], w[j + 1], a1);
            }
            float pre = a0 + a1;
            float z = isg ? (pre + pre) : pre;
            float s = fast_sigmoid(z);
            gate_sh[g] = isg ? (2.f * s - 1.f) : s;
        }
        __syncthreads();
        if (g < HDIM) {
            float iv = gate_sh[g];
            float fv = gate_sh[g + HDIM];
            float gv = gate_sh[g + 2 * HDIM];
            float ov = gate_sh[g + 3 * HDIM];
            c = fmaf(fv, c, iv * gv);
            float th = 2.f * fast_sigmoid(c + c) - 1.f;   // tanh(c)
            h_sh[g] = ov * th;
        }
        __syncthreads();
    }

    // FC head: out[b][o] = h_last . W_fc[o] + b_fc[o]
    if (g < ODIM) {
        float acc = b_fc[g];
#pragma unroll
        for (int j = 0; j < HDIM; j++)
            acc = fmaf(h_sh[j], W_fc[g * HDIM + j], acc);
        out[b * ODIM + g] = acc;
    }
}

// ============================================================
// Launch
// ============================================================
extern "C" void kernel_launch(void* const* d_in, const int* in_sizes, int n_in,
                              void* d_out, int out_size) {
    const float* x    = (const float*)d_in[0];
    const float* W_ih = (const float*)d_in[1];
    const float* W_hh = (const float*)d_in[2];
    const float* b_ih = (const float*)d_in[3];
    const float* b_hh = (const float*)d_in[4];
    const float* W_fc = (const float*)d_in[5];
    const float* b_fc = (const float*)d_in[6];
    float* out = (float*)d_out;

    prep_w<<<1, 256>>>(W_ih, b_ih, b_hh);
    transpose_x<<<dim3(BT / 32, IDIM / 32), dim3(32, 8)>>>(x);
    gemm_xproj<<<BT / MT, 256>>>();
    lstm_rec<<<BSZ, 224>>>(W_hh, W_fc, b_fc, out);
}

// round 3
// speedup vs baseline: 1.7576x; 1.7576x over previous
#include <cuda_runtime.h>

#define BSZ  512
#define TLEN 512
#define IDIM 128
#define HDIM 50
#define ODIM 10
#define GDIM 200              // 4*H
#define BT   (BSZ * TLEN)     // 262144 rows

typedef unsigned long long u64;

// ---- scratch (device globals; no allocation allowed) ----
__device__ float g_xT[IDIM * BT];        // x transposed: [k][row]
__device__ u64   g_Wt2[IDIM * GDIM];     // W_ih transposed, each value duplicated as f32x2
__device__ float g_bias[GDIM];           // b_ih + b_hh
__device__ float g_xp[BT * GDIM];        // x_proj: [row][g]

// ---- packed f32x2 helpers ----
__device__ __forceinline__ u64 pk2(float lo, float hi) {
    u64 d;
    asm("mov.b64 %0, {%1, %2};" : "=l"(d) : "f"(lo), "f"(hi));
    return d;
}
__device__ __forceinline__ void up2(u64 v, float& lo, float& hi) {
    asm("mov.b64 {%0, %1}, %2;" : "=f"(lo), "=f"(hi) : "l"(v));
}
__device__ __forceinline__ u64 ffma2(u64 a, u64 b, u64 c) {
    u64 d;
    asm("fma.rn.f32x2 %0, %1, %2, %3;" : "=l"(d) : "l"(a), "l"(b), "l"(c));
    return d;
}
__device__ __forceinline__ u64 fadd2(u64 a, u64 b) {
    u64 d;
    asm("add.rn.f32x2 %0, %1, %2;" : "=l"(d) : "l"(a), "l"(b));
    return d;
}

__device__ __forceinline__ float fast_sigmoid(float x) {
    return 1.f / (1.f + __expf(-x));
}

// ============================================================
// Kernel 0: W_ih -> g_Wt2 [k][g] duplicated pairs, bias sum
// ============================================================
__global__ void prep_w(const float* __restrict__ W_ih,
                       const float* __restrict__ b_ih,
                       const float* __restrict__ b_hh) {
    int t = threadIdx.x + blockIdx.x * 256;
    for (int idx = t; idx < IDIM * GDIM; idx += 256 * 32) {
        int g = idx / IDIM, k = idx % IDIM;
        float w = W_ih[idx];
        g_Wt2[k * GDIM + g] = pk2(w, w);
    }
    if (blockIdx.x == 0 && t < GDIM) g_bias[t] = b_ih[t] + b_hh[t];
}

// ============================================================
// Kernel 1: transpose x [BT][128] -> g_xT [128][BT]
// ============================================================
__global__ void transpose_x(const float* __restrict__ x) {
    __shared__ float tile[32][33];
    int r0 = blockIdx.x * 32;
    int k0 = blockIdx.y * 32;
    int tx = threadIdx.x, ty = threadIdx.y;   // (32, 8)
#pragma unroll
    for (int i = 0; i < 32; i += 8)
        tile[ty + i][tx] = x[(r0 + ty + i) * IDIM + k0 + tx];
    __syncthreads();
#pragma unroll
    for (int i = 0; i < 32; i += 8)
        g_xT[(k0 + ty + i) * BT + r0 + tx] = tile[tx][ty + i];
}

// ============================================================
// Kernel 2: GEMM via packed f32x2.
// g_xp[row][g] = sum_k xT[k][row] * W[g][k] + bias[g]
// Block: 64 rows x 200 gates, 224 threads (tid<200 compute 8x8).
// Accumulators packed over ROW pairs: a-operand comes naturally
// paired from xs; b-operand is the pre-duplicated weight pair.
// ============================================================
#define MT 64
#define KT 16

__global__ __launch_bounds__(224, 2) void gemm_xproj() {
    __shared__ float xs[KT][MT];        // 4 KB
    __shared__ u64   ws2[KT][GDIM];     // 25.6 KB
    const int tid = threadIdx.x;
    const int gr0 = blockIdx.x * MT;
    const int tm = tid & 7;             // row group: rows tm*8 .. tm*8+7
    const int tn = tid >> 3;            // col group: gates tn*8 .. +7 (active if <25)
    const bool active = (tid < 200);

    u64 acc[4][8];                      // [row-pair][col], each holds {row2p, row2p+1}
#pragma unroll
    for (int p = 0; p < 4; p++)
#pragma unroll
        for (int j = 0; j < 8; j++) acc[p][j] = 0ull;

    for (int kb = 0; kb < IDIM; kb += KT) {
        __syncthreads();
        // load x tile: 16 k-rows x 64 rows = 256 float4
        for (int idx = tid; idx < KT * MT / 4; idx += 224) {
            int k = idx >> 4, c = idx & 15;
            *(float4*)&xs[k][c * 4] =
                *(const float4*)&g_xT[(kb + k) * BT + gr0 + c * 4];
        }
        // load duplicated-W tile: 16 k-rows x 200 pairs = 1600 ulonglong2
        for (int idx = tid; idx < KT * GDIM / 2; idx += 224) {
            int k = idx / 100, c = idx % 100;
            *(ulonglong2*)&ws2[k][c * 2] =
                *(const ulonglong2*)&g_Wt2[(kb + k) * GDIM + c * 2];
        }
        __syncthreads();

        if (active) {
#pragma unroll
            for (int k = 0; k < KT; k++) {
                // 8 x-values for my rows, as 4 natural f32x2 pairs
                ulonglong2 xa = *(const ulonglong2*)&xs[k][tm * 8];
                ulonglong2 xb = *(const ulonglong2*)&xs[k][tm * 8 + 4];
                u64 xp2[4] = {xa.x, xa.y, xb.x, xb.y};
                // 8 duplicated weight pairs for my cols
                ulonglong2 w0 = *(const ulonglong2*)&ws2[k][tn * 8];
                ulonglong2 w1 = *(const ulonglong2*)&ws2[k][tn * 8 + 2];
                ulonglong2 w2 = *(const ulonglong2*)&ws2[k][tn * 8 + 4];
                ulonglong2 w3 = *(const ulonglong2*)&ws2[k][tn * 8 + 6];
                u64 wv[8] = {w0.x, w0.y, w1.x, w1.y, w2.x, w2.y, w3.x, w3.y};
#pragma unroll
                for (int p = 0; p < 4; p++)
#pragma unroll
                    for (int j = 0; j < 8; j++)
                        acc[p][j] = ffma2(xp2[p], wv[j], acc[p][j]);
            }
        }
    }

    if (active) {
        float bv[8];
#pragma unroll
        for (int j = 0; j < 8; j++) bv[j] = g_bias[tn * 8 + j];
#pragma unroll
        for (int p = 0; p < 4; p++) {
            float r0[8], r1[8];
#pragma unroll
            for (int j = 0; j < 8; j++) {
                float a, b;
                up2(acc[p][j], a, b);
                r0[j] = a + bv[j];
                r1[j] = b + bv[j];
            }
            int row0 = gr0 + tm * 8 + 2 * p;
            float* o0 = &g_xp[(size_t)row0 * GDIM + tn * 8];
            float* o1 = o0 + GDIM;
            *(float4*)o0       = make_float4(r0[0], r0[1], r0[2], r0[3]);
            *(float4*)(o0 + 4) = make_float4(r0[4], r0[5], r0[6], r0[7]);
            *(float4*)o1       = make_float4(r1[0], r1[1], r1[2], r1[3]);
            *(float4*)(o1 + 4) = make_float4(r1[4], r1[5], r1[6], r1[7]);
        }
    }
}

// ============================================================
// Kernel 3: LSTM recurrence + FC head, 2 batches per block.
// Grid 256, block 224. Thread g<200 owns gate g for BOTH batches:
// weights held as duplicated f32x2 pairs (100 regs), h stored as
// interleaved float2 {h_b0, h_b1}, one FFMA2 = 2 MACs.
// ============================================================
__global__ __launch_bounds__(224, 2) void lstm_rec(
    const float* __restrict__ W_hh, const float* __restrict__ W_fc,
    const float* __restrict__ b_fc, float* __restrict__ out)
{
    __shared__ alignas(16) float2 h_sh[HDIM];      // {h for b0, h for b1}
    __shared__ alignas(16) float2 gate_sh[GDIM];
    const int b0 = blockIdx.x * 2;
    const int g = threadIdx.x;

    u64 w2[HDIM];
    if (g < GDIM) {
#pragma unroll
        for (int j = 0; j < HDIM; j++) {
            float w = W_hh[g * HDIM + j];
            w2[j] = pk2(w, w);
        }
    }
    if (g < HDIM) h_sh[g] = make_float2(0.f, 0.f);
    float c0 = 0.f, c1 = 0.f;

    const float* xp0 = g_xp + (size_t)b0 * (TLEN * GDIM);
    const float* xp1 = xp0 + (size_t)(TLEN * GDIM);
    float xc0 = 0.f, xc1 = 0.f;
    if (g < GDIM) { xc0 = xp0[g]; xc1 = xp1[g]; }
    const bool isg = (g >= 2 * HDIM && g < 3 * HDIM);   // tanh gate
    __syncthreads();

    for (int t = 0; t < TLEN; t++) {
        if (g < GDIM) {
            u64 accA = pk2(xc0, xc1);
            u64 accB = 0ull;
            if (t + 1 < TLEN) {                          // prefetch next step
                xc0 = xp0[(t + 1) * GDIM + g];
                xc1 = xp1[(t + 1) * GDIM + g];
            }
#pragma unroll
            for (int j = 0; j < HDIM; j += 2) {
                ulonglong2 hv = *(const ulonglong2*)(h_sh + j);  // {h01[j], h01[j+1]}
                accA = ffma2(hv.x, w2[j],     accA);
                accB = ffma2(hv.y, w2[j + 1], accB);
            }
            float a0, a1;
            up2(fadd2(accA, accB), a0, a1);
            float z0 = isg ? (a0 + a0) : a0;
            float z1 = isg ? (a1 + a1) : a1;
            float s0 = fast_sigmoid(z0);
            float s1 = fast_sigmoid(z1);
            float r0 = isg ? (2.f * s0 - 1.f) : s0;
            float r1 = isg ? (2.f * s1 - 1.f) : s1;
            gate_sh[g] = make_float2(r0, r1);
        }
        __syncthreads();
        if (g < HDIM) {
            float2 iv = gate_sh[g];
            float2 fv = gate_sh[g + HDIM];
            float2 gv = gate_sh[g + 2 * HDIM];
            float2 ov = gate_sh[g + 3 * HDIM];
            c0 = fmaf(fv.x, c0, iv.x * gv.x);
            c1 = fmaf(fv.y, c1, iv.y * gv.y);
            float th0 = 2.f * fast_sigmoid(c0 + c0) - 1.f;   // tanh(c0)
            float th1 = 2.f * fast_sigmoid(c1 + c1) - 1.f;
            h_sh[g] = make_float2(ov.x * th0, ov.y * th1);
        }
        __syncthreads();
    }

    // FC head for both batches
    if (g < ODIM) {
        float a0 = b_fc[g], a1 = a0;
#pragma unroll
        for (int j = 0; j < HDIM; j++) {
            float2 h = h_sh[j];
            float w = W_fc[g * HDIM + j];
            a0 = fmaf(h.x, w, a0);
            a1 = fmaf(h.y, w, a1);
        }
        out[b0 * ODIM + g]       = a0;
        out[(b0 + 1) * ODIM + g] = a1;
    }
}

// ============================================================
// Launch
// ============================================================
extern "C" void kernel_launch(void* const* d_in, const int* in_sizes, int n_in,
                              void* d_out, int out_size) {
    const float* x    = (const float*)d_in[0];
    const float* W_ih = (const float*)d_in[1];
    const float* W_hh = (const float*)d_in[2];
    const float* b_ih = (const float*)d_in[3];
    const float* b_hh = (const float*)d_in[4];
    const float* W_fc = (const float*)d_in[5];
    const float* b_fc = (const float*)d_in[6];
    float* out = (float*)d_out;

    prep_w<<<32, 256>>>(W_ih, b_ih, b_hh);
    transpose_x<<<dim3(BT / 32, IDIM / 32), dim3(32, 8)>>>(x);
    gemm_xproj<<<BT / MT, 224>>>();
    lstm_rec<<<BSZ / 2, 224>>>(W_hh, W_fc, b_fc, out);
}